// round 1
// baseline (speedup 1.0000x reference)
#include <cuda_runtime.h>
#include <math.h>

#define BATCH  2
#define SEQ    2048
#define DMODEL 256
#define DINNER 512
#define DSTATE 16
#define NTOK   (BATCH*SEQ)   // 4096

// ---------------- scratch (no allocations allowed) ----------------
__device__ float g_hn[NTOK*DMODEL];       // rmsnorm output        (4 MB)
__device__ float g_xz[NTOK*2*DINNER];     // in_proj output        (16 MB)
__device__ float g_xc[NTOK*DINNER];       // conv+silu output      (8 MB)
__device__ float g_dbl[NTOK*48];          // x_proj output (dt|B|C)
__device__ float g_delta[NTOK*DINNER];    // softplus(dt_proj)     (8 MB)
__device__ float g_yact[NTOK*DINNER];     // y * silu(z)           (8 MB)

// ---------------- 1) RMSNorm (reads transposed x) ----------------
__global__ __launch_bounds__(256) void rmsnorm_kernel(
    const float* __restrict__ x, const float* __restrict__ w)
{
    int t = blockIdx.x;                 // token = b*SEQ + l
    int b = t >> 11, l = t & 2047;
    int c = threadIdx.x;
    float v = x[(size_t)b*DMODEL*SEQ + (size_t)c*SEQ + l];
    float s = v*v;
    #pragma unroll
    for (int o = 16; o > 0; o >>= 1) s += __shfl_xor_sync(0xffffffffu, s, o);
    __shared__ float red[8];
    __shared__ float rs_s;
    if ((c & 31) == 0) red[c >> 5] = s;
    __syncthreads();
    if (c == 0) {
        float tot = 0.f;
        #pragma unroll
        for (int i = 0; i < 8; i++) tot += red[i];
        rs_s = rsqrtf(tot * (1.0f/DMODEL) + 1e-5f);
    }
    __syncthreads();
    g_hn[t*DMODEL + c] = v * rs_s * w[c];
}

// ---------------- generic fp32 GEMM:  C = A(MxK) * B(NxK)^T ----------------
// MODE 0: plain row-major store.  MODE 1: out_proj epilogue — write transposed
// into (B, DMODEL, 1, SEQ) layout with residual add.
template<int MODE>
__global__ __launch_bounds__(256) void sgemm_tn(
    const float* __restrict__ A, const float* __restrict__ B,
    float* __restrict__ C, int M, int N, int K,
    const float* __restrict__ resid)
{
    __shared__ float As[8][128];
    __shared__ float Bs[8][128];
    int tid  = threadIdx.x;
    int tRow = tid >> 4, tCol = tid & 15;
    int rowBase = blockIdx.x * 128;
    int colBase = blockIdx.y * 128;

    float acc[8][8];
    #pragma unroll
    for (int i = 0; i < 8; i++)
        #pragma unroll
        for (int j = 0; j < 8; j++) acc[i][j] = 0.f;

    int ldRow = tid >> 1;
    int ldCol = (tid & 1) * 4;
    const float* Ag = A + (size_t)(rowBase + ldRow) * K + ldCol;
    int  bn = colBase + ldRow;
    bool bv = bn < N;
    const float* Bg = B + (size_t)(bv ? bn : 0) * K + ldCol;

    for (int kt = 0; kt < K; kt += 8) {
        float4 av  = *(const float4*)(Ag + kt);
        float4 bvv = bv ? *(const float4*)(Bg + kt) : make_float4(0.f,0.f,0.f,0.f);
        As[ldCol+0][ldRow] = av.x;  As[ldCol+1][ldRow] = av.y;
        As[ldCol+2][ldRow] = av.z;  As[ldCol+3][ldRow] = av.w;
        Bs[ldCol+0][ldRow] = bvv.x; Bs[ldCol+1][ldRow] = bvv.y;
        Bs[ldCol+2][ldRow] = bvv.z; Bs[ldCol+3][ldRow] = bvv.w;
        __syncthreads();
        #pragma unroll
        for (int k = 0; k < 8; k++) {
            float4 a0 = *(const float4*)&As[k][tRow*8];
            float4 a1 = *(const float4*)&As[k][tRow*8+4];
            float4 b0 = *(const float4*)&Bs[k][tCol*8];
            float4 b1 = *(const float4*)&Bs[k][tCol*8+4];
            float ar[8] = {a0.x,a0.y,a0.z,a0.w,a1.x,a1.y,a1.z,a1.w};
            float br[8] = {b0.x,b0.y,b0.z,b0.w,b1.x,b1.y,b1.z,b1.w};
            #pragma unroll
            for (int i = 0; i < 8; i++)
                #pragma unroll
                for (int j = 0; j < 8; j++)
                    acc[i][j] = fmaf(ar[i], br[j], acc[i][j]);
        }
        __syncthreads();
    }

    #pragma unroll
    for (int i = 0; i < 8; i++) {
        int row = rowBase + tRow*8 + i;
        #pragma unroll
        for (int j = 0; j < 8; j++) {
            int col = colBase + tCol*8 + j;
            if (col < N) {
                if (MODE == 0) {
                    C[(size_t)row*N + col] = acc[i][j];
                } else {
                    int b = row >> 11, l = row & 2047;
                    size_t oi = (size_t)b*DMODEL*SEQ + (size_t)col*SEQ + l;
                    C[oi] = acc[i][j] + resid[oi];
                }
            }
        }
    }
}

// ---------------- 3) depthwise causal conv (width 4) + SiLU ----------------
__global__ __launch_bounds__(256) void conv_silu_kernel(
    const float* __restrict__ cw, const float* __restrict__ cb)
{
    int idx = blockIdx.x*256 + threadIdx.x;   // < NTOK*DINNER
    int t = idx >> 9;
    int d = idx & 511;
    int l = t & 2047;
    float acc = cb[d];
    const float* w = cw + d*4;
    #pragma unroll
    for (int j = 0; j < 4; j++) {
        int ls = l - 3 + j;
        if (ls >= 0) acc = fmaf(w[j], g_xz[(size_t)(t-3+j)*1024 + d], acc);
    }
    acc = acc / (1.f + __expf(-acc));         // silu
    g_xc[idx] = acc;
}

// ---------------- 5) delta = softplus(dt @ dt_proj_w^T + b) ----------------
__global__ __launch_bounds__(256) void dtproj_kernel(
    const float* __restrict__ W, const float* __restrict__ bias)
{
    int t = blockIdx.x;
    int d = blockIdx.y*256 + threadIdx.x;
    __shared__ float st[16];
    if (threadIdx.x < 16) st[threadIdx.x] = g_dbl[t*48 + threadIdx.x];
    __syncthreads();
    float acc = bias[d];
    const float4* w4 = (const float4*)(W + (size_t)d*16);
    #pragma unroll
    for (int q = 0; q < 4; q++) {
        float4 w = w4[q];
        acc = fmaf(st[q*4+0], w.x, acc);
        acc = fmaf(st[q*4+1], w.y, acc);
        acc = fmaf(st[q*4+2], w.z, acc);
        acc = fmaf(st[q*4+3], w.w, acc);
    }
    acc = (acc > 20.f) ? acc : log1pf(__expf(acc));   // softplus
    g_delta[t*DINNER + d] = acc;
}

// ---------------- 6) selective scan + D skip + gate ----------------
// Block = (b, 8 d-channels). lane = d_local*16 + n. 32-step chunks:
// recurrence runs in registers, h*C staged to smem, then cooperative
// n-reduction + gating fused.
__global__ __launch_bounds__(128) void scan_kernel(
    const float* __restrict__ A_log, const float* __restrict__ Dp)
{
    int b   = blockIdx.y;
    int d0  = blockIdx.x * 8;
    int tid = threadIdx.x;
    int dl  = tid >> 4, n = tid & 15;
    int d   = d0 + dl;

    float a = -expf(A_log[d*DSTATE + n]);
    float h = 0.f;

    __shared__ float sdelta[32][8], sx[32][8], sB[32][16], sC[32][16];
    __shared__ float shc[32][128];

    for (int l0 = 0; l0 < SEQ; l0 += 32) {
        #pragma unroll
        for (int i = tid; i < 256; i += 128) {
            int t = i >> 3, dd = i & 7;
            int gt = b*SEQ + l0 + t;
            sdelta[t][dd] = g_delta[(size_t)gt*DINNER + d0 + dd];
            sx[t][dd]     = g_xc  [(size_t)gt*DINNER + d0 + dd];
        }
        #pragma unroll
        for (int i = tid; i < 512; i += 128) {
            int t = i >> 4, nn = i & 15;
            int gt = b*SEQ + l0 + t;
            sB[t][nn] = g_dbl[gt*48 + 16 + nn];
            sC[t][nn] = g_dbl[gt*48 + 32 + nn];
        }
        __syncthreads();

        #pragma unroll
        for (int t = 0; t < 32; t++) {
            float dlt = sdelta[t][dl];
            float dA  = __expf(dlt * a);
            float dbx = dlt * sB[t][n] * sx[t][dl];
            h = fmaf(dA, h, dbx);
            shc[t][tid] = h * sC[t][n];
        }
        __syncthreads();

        #pragma unroll
        for (int i = tid; i < 256; i += 128) {
            int t = i >> 3, dd = i & 7;
            float s = 0.f;
            #pragma unroll
            for (int q = 0; q < 16; q++) s += shc[t][dd*16 + q];
            int d2 = d0 + dd;
            int gt = b*SEQ + l0 + t;
            float yv = fmaf(sx[t][dd], Dp[d2], s);
            float zv = g_xz[(size_t)gt*1024 + DINNER + d2];
            yv *= zv / (1.f + __expf(-zv));                 // * silu(z)
            g_yact[(size_t)gt*DINNER + d2] = yv;
        }
        __syncthreads();
    }
}

// ---------------- launch ----------------
extern "C" void kernel_launch(void* const* d_in, const int* in_sizes, int n_in,
                              void* d_out, int out_size)
{
    const float* x          = (const float*)d_in[0];
    const float* norm_w     = (const float*)d_in[1];
    const float* in_proj_w  = (const float*)d_in[2];
    const float* conv_w     = (const float*)d_in[3];
    const float* conv_b     = (const float*)d_in[4];
    const float* x_proj_w   = (const float*)d_in[5];
    const float* dt_proj_w  = (const float*)d_in[6];
    const float* dt_proj_b  = (const float*)d_in[7];
    const float* A_log      = (const float*)d_in[8];
    const float* Dp         = (const float*)d_in[9];
    const float* out_proj_w = (const float*)d_in[10];
    float* out = (float*)d_out;
    (void)in_sizes; (void)n_in; (void)out_size;

    float *hn, *xz, *xc, *dbl, *yact;
    cudaGetSymbolAddress((void**)&hn,   g_hn);
    cudaGetSymbolAddress((void**)&xz,   g_xz);
    cudaGetSymbolAddress((void**)&xc,   g_xc);
    cudaGetSymbolAddress((void**)&dbl,  g_dbl);
    cudaGetSymbolAddress((void**)&yact, g_yact);

    // 1) rmsnorm
    rmsnorm_kernel<<<NTOK, 256>>>(x, norm_w);
    // 2) xz = hn @ in_proj_w^T           (4096 x 1024 x 256)
    sgemm_tn<0><<<dim3(32, 8), 256>>>(hn, in_proj_w, xz, NTOK, 2*DINNER, DMODEL, nullptr);
    // 3) xc = silu(causal_conv(xin))
    conv_silu_kernel<<<NTOK*DINNER/256, 256>>>(conv_w, conv_b);
    // 4) dbl = xc @ x_proj_w^T           (4096 x 48 x 512)
    sgemm_tn<0><<<dim3(32, 1), 256>>>(xc, x_proj_w, dbl, NTOK, 48, DINNER, nullptr);
    // 5) delta = softplus(dt @ dt_proj_w^T + b)
    dtproj_kernel<<<dim3(NTOK, 2), 256>>>(dt_proj_w, dt_proj_b);
    // 6) selective scan + gate
    scan_kernel<<<dim3(DINNER/8, BATCH), 128>>>(A_log, Dp);
    // 7) out = yact @ out_proj_w^T + residual, transposed to (B,C,1,L)
    sgemm_tn<1><<<dim3(32, 2), 256>>>(yact, out_proj_w, out, NTOK, DMODEL, DINNER, x);
}

// round 2
// speedup vs baseline: 1.7334x; 1.7334x over previous
#include <cuda_runtime.h>
#include <math.h>

#define BATCH  2
#define SEQ    2048
#define DMODEL 256
#define DINNER 512
#define DSTATE 16
#define NTOK   (BATCH*SEQ)   // 4096

// ---------------- scratch (no allocations allowed) ----------------
__device__ float g_hn[NTOK*DMODEL];       // rmsnorm output
__device__ float g_xz[NTOK*2*DINNER];     // in_proj output
__device__ float g_xc[NTOK*DINNER];       // conv+silu output
__device__ float g_dbl[NTOK*48];          // x_proj output (dt|B|C)
__device__ float g_delta[NTOK*DINNER];    // softplus(dt_proj)
__device__ float g_yact[NTOK*DINNER];     // y * silu(z)

// ---------------- 1) RMSNorm (reads transposed x) ----------------
__global__ __launch_bounds__(256) void rmsnorm_kernel(
    const float* __restrict__ x, const float* __restrict__ w)
{
    int t = blockIdx.x;                 // token = b*SEQ + l
    int b = t >> 11, l = t & 2047;
    int c = threadIdx.x;
    float v = x[(size_t)b*DMODEL*SEQ + (size_t)c*SEQ + l];
    float s = v*v;
    #pragma unroll
    for (int o = 16; o > 0; o >>= 1) s += __shfl_xor_sync(0xffffffffu, s, o);
    __shared__ float red[8];
    __shared__ float rs_s;
    if ((c & 31) == 0) red[c >> 5] = s;
    __syncthreads();
    if (c == 0) {
        float tot = 0.f;
        #pragma unroll
        for (int i = 0; i < 8; i++) tot += red[i];
        rs_s = rsqrtf(tot * (1.0f/DMODEL) + 1e-5f);
    }
    __syncthreads();
    g_hn[t*DMODEL + c] = v * rs_s * w[c];
}

// ---------------- tf32 tensor-core GEMM:  C = A(MxK) * B(NxK)^T ----------------
// Tile 128x64x32, 8 warps (4 m x 2 n), warp tile 32x32 via m16n8k8.
// MODE 0: row-major store. MODE 1: out_proj epilogue (transpose + residual).
__device__ __forceinline__ unsigned f2tf(float v) {
    unsigned o; asm("cvt.rna.tf32.f32 %0, %1;" : "=r"(o) : "f"(v)); return o;
}

template<int MODE>
__global__ __launch_bounds__(256) void mma_tn(
    const float* __restrict__ A, const float* __restrict__ B,
    float* __restrict__ C, int M, int N, int K,
    const float* __restrict__ resid)
{
    __shared__ unsigned As[128][36];   // [m][k], stride 36 -> conflict-free frag loads
    __shared__ unsigned Bs[64][36];    // [n][k]
    int tid  = threadIdx.x;
    int lane = tid & 31, w = tid >> 5;
    int wm = w & 3, wn = w >> 2;       // 4 x 2 warp grid
    int rowBase = blockIdx.x * 128;
    int colBase = blockIdx.y * 64;

    float acc[2][4][4];
    #pragma unroll
    for (int mt = 0; mt < 2; mt++)
        #pragma unroll
        for (int nt = 0; nt < 4; nt++)
            #pragma unroll
            for (int q = 0; q < 4; q++) acc[mt][nt][q] = 0.f;

    int lr = tid >> 3;          // 0..31
    int lc = (tid & 7) * 4;     // 0,4,...,28

    for (int kt = 0; kt < K; kt += 32) {
        #pragma unroll
        for (int i = 0; i < 4; i++) {
            int r = lr + i*32;
            float4 v = *(const float4*)(A + (size_t)(rowBase + r)*K + kt + lc);
            *(uint4*)&As[r][lc] = make_uint4(f2tf(v.x), f2tf(v.y), f2tf(v.z), f2tf(v.w));
        }
        #pragma unroll
        for (int i = 0; i < 2; i++) {
            int r = lr + i*32;
            int bn = colBase + r;
            float4 v = (bn < N) ? *(const float4*)(B + (size_t)bn*K + kt + lc)
                                : make_float4(0.f,0.f,0.f,0.f);
            *(uint4*)&Bs[r][lc] = make_uint4(f2tf(v.x), f2tf(v.y), f2tf(v.z), f2tf(v.w));
        }
        __syncthreads();

        #pragma unroll
        for (int kk = 0; kk < 32; kk += 8) {
            unsigned a[2][4], bf[4][2];
            #pragma unroll
            for (int mt = 0; mt < 2; mt++) {
                int r = wm*32 + mt*16 + (lane >> 2);
                int c = kk + (lane & 3);
                a[mt][0] = As[r  ][c  ];
                a[mt][1] = As[r+8][c  ];
                a[mt][2] = As[r  ][c+4];
                a[mt][3] = As[r+8][c+4];
            }
            #pragma unroll
            for (int nt = 0; nt < 4; nt++) {
                int n = wn*32 + nt*8 + (lane >> 2);
                int c = kk + (lane & 3);
                bf[nt][0] = Bs[n][c];
                bf[nt][1] = Bs[n][c+4];
            }
            #pragma unroll
            for (int mt = 0; mt < 2; mt++)
                #pragma unroll
                for (int nt = 0; nt < 4; nt++)
                    asm volatile(
                        "mma.sync.aligned.m16n8k8.row.col.f32.tf32.tf32.f32 "
                        "{%0,%1,%2,%3}, {%4,%5,%6,%7}, {%8,%9}, {%0,%1,%2,%3};"
                        : "+f"(acc[mt][nt][0]), "+f"(acc[mt][nt][1]),
                          "+f"(acc[mt][nt][2]), "+f"(acc[mt][nt][3])
                        : "r"(a[mt][0]), "r"(a[mt][1]), "r"(a[mt][2]), "r"(a[mt][3]),
                          "r"(bf[nt][0]), "r"(bf[nt][1]));
        }
        __syncthreads();
    }

    #pragma unroll
    for (int mt = 0; mt < 2; mt++) {
        #pragma unroll
        for (int nt = 0; nt < 4; nt++) {
            int r0 = rowBase + wm*32 + mt*16 + (lane >> 2);
            int c0 = colBase + wn*32 + nt*8 + (lane & 3)*2;
            if (MODE == 0) {
                if (c0 < N) {
                    *(float2*)&C[(size_t)r0*N + c0] =
                        make_float2(acc[mt][nt][0], acc[mt][nt][1]);
                    *(float2*)&C[(size_t)(r0+8)*N + c0] =
                        make_float2(acc[mt][nt][2], acc[mt][nt][3]);
                }
            } else {
                int b0 = r0 >> 11, l0 = r0 & 2047;
                size_t base = (size_t)b0*DMODEL*SEQ + (size_t)c0*SEQ;
                size_t o0 = base + l0;
                size_t o8 = base + l0 + 8;        // r0+8 stays in same batch (tile-aligned)
                C[o0]       = acc[mt][nt][0] + resid[o0];
                C[o0 + SEQ] = acc[mt][nt][1] + resid[o0 + SEQ];
                C[o8]       = acc[mt][nt][2] + resid[o8];
                C[o8 + SEQ] = acc[mt][nt][3] + resid[o8 + SEQ];
            }
        }
    }
}

// ---------------- 3) depthwise causal conv (width 4) + SiLU ----------------
__global__ __launch_bounds__(256) void conv_silu_kernel(
    const float* __restrict__ cw, const float* __restrict__ cb)
{
    int idx = blockIdx.x*256 + threadIdx.x;   // < NTOK*DINNER
    int t = idx >> 9;
    int d = idx & 511;
    int l = t & 2047;
    float acc = cb[d];
    const float* w = cw + d*4;
    #pragma unroll
    for (int j = 0; j < 4; j++) {
        int ls = l - 3 + j;
        if (ls >= 0) acc = fmaf(w[j], g_xz[(size_t)(t-3+j)*1024 + d], acc);
    }
    acc = acc / (1.f + __expf(-acc));         // silu
    g_xc[idx] = acc;
}

// ---------------- 5) delta = softplus(dt @ dt_proj_w^T + b) ----------------
// 256 blocks x 16 tokens; W rows held in registers (2 rows/thread).
__global__ __launch_bounds__(256) void dtproj_kernel(
    const float* __restrict__ W, const float* __restrict__ bias)
{
    int t0 = blockIdx.x * 16;
    int tid = threadIdx.x;
    int d = tid * 2;
    __shared__ float st[16][17];
    {
        int t = tid >> 4, r = tid & 15;
        st[t][r] = g_dbl[(t0 + t)*48 + r];
    }
    __syncthreads();

    const float4* w0 = (const float4*)(W + (size_t)d*16);
    const float4* w1 = (const float4*)(W + (size_t)(d+1)*16);
    float4 wa0 = w0[0], wa1 = w0[1], wa2 = w0[2], wa3 = w0[3];
    float4 wb0 = w1[0], wb1 = w1[1], wb2 = w1[2], wb3 = w1[3];
    float b0 = bias[d], b1 = bias[d+1];

    #pragma unroll 4
    for (int t = 0; t < 16; t++) {
        const float* s = st[t];
        float a0 = b0, a1 = b1;
        a0 = fmaf(s[0],wa0.x,a0); a0 = fmaf(s[1],wa0.y,a0); a0 = fmaf(s[2],wa0.z,a0); a0 = fmaf(s[3],wa0.w,a0);
        a0 = fmaf(s[4],wa1.x,a0); a0 = fmaf(s[5],wa1.y,a0); a0 = fmaf(s[6],wa1.z,a0); a0 = fmaf(s[7],wa1.w,a0);
        a0 = fmaf(s[8],wa2.x,a0); a0 = fmaf(s[9],wa2.y,a0); a0 = fmaf(s[10],wa2.z,a0); a0 = fmaf(s[11],wa2.w,a0);
        a0 = fmaf(s[12],wa3.x,a0); a0 = fmaf(s[13],wa3.y,a0); a0 = fmaf(s[14],wa3.z,a0); a0 = fmaf(s[15],wa3.w,a0);
        a1 = fmaf(s[0],wb0.x,a1); a1 = fmaf(s[1],wb0.y,a1); a1 = fmaf(s[2],wb0.z,a1); a1 = fmaf(s[3],wb0.w,a1);
        a1 = fmaf(s[4],wb1.x,a1); a1 = fmaf(s[5],wb1.y,a1); a1 = fmaf(s[6],wb1.z,a1); a1 = fmaf(s[7],wb1.w,a1);
        a1 = fmaf(s[8],wb2.x,a1); a1 = fmaf(s[9],wb2.y,a1); a1 = fmaf(s[10],wb2.z,a1); a1 = fmaf(s[11],wb2.w,a1);
        a1 = fmaf(s[12],wb3.x,a1); a1 = fmaf(s[13],wb3.y,a1); a1 = fmaf(s[14],wb3.z,a1); a1 = fmaf(s[15],wb3.w,a1);
        a0 = (a0 > 20.f) ? a0 : log1pf(__expf(a0));
        a1 = (a1 > 20.f) ? a1 : log1pf(__expf(a1));
        *(float2*)&g_delta[(size_t)(t0+t)*DINNER + d] = make_float2(a0, a1);
    }
}

// ---------------- 6) selective scan + D skip + gate ----------------
__global__ __launch_bounds__(128) void scan_kernel(
    const float* __restrict__ A_log, const float* __restrict__ Dp)
{
    int b   = blockIdx.y;
    int d0  = blockIdx.x * 8;
    int tid = threadIdx.x;
    int dl  = tid >> 4, n = tid & 15;
    int d   = d0 + dl;

    float a = -expf(A_log[d*DSTATE + n]);
    float h = 0.f;

    __shared__ float sdelta[32][8], sx[32][8], sB[32][16], sC[32][16];
    __shared__ float shc[32][128];

    for (int l0 = 0; l0 < SEQ; l0 += 32) {
        #pragma unroll
        for (int i = tid; i < 256; i += 128) {
            int t = i >> 3, dd = i & 7;
            int gt = b*SEQ + l0 + t;
            sdelta[t][dd] = g_delta[(size_t)gt*DINNER + d0 + dd];
            sx[t][dd]     = g_xc  [(size_t)gt*DINNER + d0 + dd];
        }
        #pragma unroll
        for (int i = tid; i < 512; i += 128) {
            int t = i >> 4, nn = i & 15;
            int gt = b*SEQ + l0 + t;
            sB[t][nn] = g_dbl[gt*48 + 16 + nn];
            sC[t][nn] = g_dbl[gt*48 + 32 + nn];
        }
        __syncthreads();

        #pragma unroll
        for (int t = 0; t < 32; t++) {
            float dlt = sdelta[t][dl];
            float dA  = __expf(dlt * a);
            float dbx = dlt * sB[t][n] * sx[t][dl];
            h = fmaf(dA, h, dbx);
            shc[t][tid] = h * sC[t][n];
        }
        __syncthreads();

        #pragma unroll
        for (int i = tid; i < 256; i += 128) {
            int t = i >> 3, dd = i & 7;
            float s = 0.f;
            #pragma unroll
            for (int q = 0; q < 16; q++) s += shc[t][dd*16 + q];
            int d2 = d0 + dd;
            int gt = b*SEQ + l0 + t;
            float yv = fmaf(sx[t][dd], Dp[d2], s);
            float zv = g_xz[(size_t)gt*1024 + DINNER + d2];
            yv *= zv / (1.f + __expf(-zv));                 // * silu(z)
            g_yact[(size_t)gt*DINNER + d2] = yv;
        }
        __syncthreads();
    }
}

// ---------------- launch ----------------
extern "C" void kernel_launch(void* const* d_in, const int* in_sizes, int n_in,
                              void* d_out, int out_size)
{
    const float* x          = (const float*)d_in[0];
    const float* norm_w     = (const float*)d_in[1];
    const float* in_proj_w  = (const float*)d_in[2];
    const float* conv_w     = (const float*)d_in[3];
    const float* conv_b     = (const float*)d_in[4];
    const float* x_proj_w   = (const float*)d_in[5];
    const float* dt_proj_w  = (const float*)d_in[6];
    const float* dt_proj_b  = (const float*)d_in[7];
    const float* A_log      = (const float*)d_in[8];
    const float* Dp         = (const float*)d_in[9];
    const float* out_proj_w = (const float*)d_in[10];
    float* out = (float*)d_out;
    (void)in_sizes; (void)n_in; (void)out_size;

    float *hn, *xz, *xc, *dbl, *yact;
    cudaGetSymbolAddress((void**)&hn,   g_hn);
    cudaGetSymbolAddress((void**)&xz,   g_xz);
    cudaGetSymbolAddress((void**)&xc,   g_xc);
    cudaGetSymbolAddress((void**)&dbl,  g_dbl);
    cudaGetSymbolAddress((void**)&yact, g_yact);

    // 1) rmsnorm
    rmsnorm_kernel<<<NTOK, 256>>>(x, norm_w);
    // 2) xz = hn @ in_proj_w^T           (4096 x 1024 x 256)
    mma_tn<0><<<dim3(32, 16), 256>>>(hn, in_proj_w, xz, NTOK, 2*DINNER, DMODEL, nullptr);
    // 3) xc = silu(causal_conv(xin))
    conv_silu_kernel<<<NTOK*DINNER/256, 256>>>(conv_w, conv_b);
    // 4) dbl = xc @ x_proj_w^T           (4096 x 48 x 512)
    mma_tn<0><<<dim3(32, 1), 256>>>(xc, x_proj_w, dbl, NTOK, 48, DINNER, nullptr);
    // 5) delta = softplus(dt @ dt_proj_w^T + b)
    dtproj_kernel<<<NTOK/16, 256>>>(dt_proj_w, dt_proj_b);
    // 6) selective scan + gate
    scan_kernel<<<dim3(DINNER/8, BATCH), 128>>>(A_log, Dp);
    // 7) out = yact @ out_proj_w^T + residual, transposed to (B,C,1,L)
    mma_tn<1><<<dim3(32, 4), 256>>>(yact, out_proj_w, out, NTOK, DMODEL, DINNER, x);
}